// round 1
// baseline (speedup 1.0000x reference)
#include <cuda_runtime.h>
#include <cstdint>

#define T_STEPS 2048
#define BATCH   512
#define DIM     128
#define HID     128
#define NG      32          // 4 gates * 8 wires
#define GEMM_SMEM_BYTES ((128*132 + 32*128 + 32) * 4)

// 134 MB scratch for Zx = X @ Wx^T + b  (layout: [t*B+b][32])
__device__ float g_Z[(size_t)T_STEPS * BATCH * NG];
__device__ float g_whsum[NG];

__device__ __forceinline__ float tanh_fast(float x) {
    float r; asm("tanh.approx.f32 %0, %1;" : "=f"(r) : "f"(x)); return r;
}

// ---------------- whsum: row sums of the H-part of each gate's W ----------------
__global__ void whsum_kernel(const float* __restrict__ Wf, const float* __restrict__ Wi,
                             const float* __restrict__ Wu, const float* __restrict__ Wo) {
    int l = threadIdx.x;              // 0..31
    int g = l >> 3, w = l & 7;
    const float* W = (g == 0) ? Wf : (g == 1) ? Wi : (g == 2) ? Wu : Wo;
    const float* row = W + w * (DIM + HID) + DIM;
    float s = 0.f;
#pragma unroll
    for (int k = 0; k < HID; k++) s += row[k];
    g_whsum[l] = s;
}

// ---------------- GEMM: Z[m][n] = sum_k X[m][k] * W_n[k] + b_n ----------------
// M = T*B = 1,048,576 rows, N = 32, K = 128. 128-row tiles, 256 threads.
__global__ void __launch_bounds__(256, 2) gemm_kernel(
    const float* __restrict__ X,
    const float* __restrict__ Wf, const float* __restrict__ bf,
    const float* __restrict__ Wi, const float* __restrict__ bi,
    const float* __restrict__ Wu, const float* __restrict__ bu,
    const float* __restrict__ Wo, const float* __restrict__ bo) {
    extern __shared__ float sm[];
    float* Xs = sm;                    // [128][132]  (pitch 132 -> conflict-free f4)
    float* Ws = sm + 128 * 132;        // [32][128]
    float* bs = Ws + 32 * 128;         // [32]
    const int tid = threadIdx.x;
    const size_t m0 = (size_t)blockIdx.x * 128;

    // Stage W (gate-major columns: n = g*8+w), first 128 columns only (x-part)
#pragma unroll
    for (int i = 0; i < 16; i++) {
        int idx = tid + i * 256;       // 0..4095
        int n = idx >> 7, k = idx & 127;
        int g = n >> 3, w = n & 7;
        const float* W = (g == 0) ? Wf : (g == 1) ? Wi : (g == 2) ? Wu : Wo;
        Ws[n * 128 + k] = W[w * 256 + k];
    }
    if (tid < 32) {
        int g = tid >> 3, w = tid & 7;
        const float* bb = (g == 0) ? bf : (g == 1) ? bi : (g == 2) ? bu : bo;
        bs[tid] = bb[w];
    }
    // Stage X tile (128 rows x 128 floats) as float4
#pragma unroll
    for (int i = 0; i < 16; i++) {
        int idx = tid + i * 256;       // float4 index 0..4095
        int m = idx >> 5, j = idx & 31;
        float4 v = *(const float4*)(X + (m0 + m) * 128 + j * 4);
        *(float4*)(Xs + m * 132 + j * 4) = v;
    }
    __syncthreads();

    const int lane = tid & 31;
    const int n0 = (tid >> 5) * 4;     // warp-uniform n block
    float acc[4][4] = {};
#pragma unroll 4
    for (int k = 0; k < 128; k += 4) {
        float4 a[4], b[4];
#pragma unroll
        for (int j = 0; j < 4; j++) a[j] = *(const float4*)(Xs + (lane + 32 * j) * 132 + k);
#pragma unroll
        for (int i = 0; i < 4; i++) b[i] = *(const float4*)(Ws + (n0 + i) * 128 + k);
#pragma unroll
        for (int j = 0; j < 4; j++)
#pragma unroll
            for (int i = 0; i < 4; i++) {
                acc[j][i] = fmaf(a[j].x, b[i].x, acc[j][i]);
                acc[j][i] = fmaf(a[j].y, b[i].y, acc[j][i]);
                acc[j][i] = fmaf(a[j].z, b[i].z, acc[j][i]);
                acc[j][i] = fmaf(a[j].w, b[i].w, acc[j][i]);
            }
    }
    __syncthreads();
    // Stage Z tile in smem (pitch 36) so global stores are fully coalesced
    float* Zs = sm;                    // reuse Xs region (bs region is disjoint)
#pragma unroll
    for (int j = 0; j < 4; j++)
#pragma unroll
        for (int i = 0; i < 4; i++)
            Zs[(lane + 32 * j) * 36 + n0 + i] = acc[j][i] + bs[n0 + i];
    __syncthreads();
#pragma unroll
    for (int i = 0; i < 4; i++) {
        int idx = tid + i * 256;       // 0..1023 float4s
        int m = idx >> 3, q = idx & 7;
        float4 v = *(const float4*)(Zs + m * 36 + q * 4);
        *(float4*)(g_Z + (m0 + m) * 32 + q * 4) = v;
    }
}

// ---------------- Recurrence: one warp per batch sample ----------------
// lane l: gate g = l>>3, wire w = l&7.
// qgate = mean(sin^2(z/2)) = 0.5 - (sum_w cos z_w)/16
// sigmoid(q) = 0.5 + 0.5*tanh(q/2); tanh gate uses tanh(q) directly.
__global__ void __launch_bounds__(32) rnn_kernel(float* __restrict__ out) {
    const int b = blockIdx.x;          // 512 chains
    const int l = threadIdx.x;
    const int g = l >> 3;
    const int w = l & 7;
    const float whs = g_whsum[l];
    // fold the /2 for sigmoid gates into the q affine: arg = off + scale*sumcos
    const float scale = (g == 2) ? -(1.f / 16.f) : -(1.f / 32.f);
    const float off   = (g == 2) ? 0.5f : 0.25f;
    const bool  isU   = (g == 2);
    const bool  g0 = (g == 0), g1 = (g == 1), g2 = (g == 2);

    const float* zp = g_Z + (size_t)b * NG + l;
    const size_t ZS = (size_t)BATCH * NG;    // 16384 floats per t
    const size_t OS = (size_t)BATCH * HID;   // 65536 floats per t
    float* op = out + (size_t)b * HID + (size_t)l * 4;

    float s = 0.f, c = 0.f;
    float zbuf[8];
#pragma unroll
    for (int p = 0; p < 8; p++) zbuf[p] = zp[(size_t)p * ZS];

    for (int t0 = 0; t0 < T_STEPS; t0 += 8) {
#pragma unroll
        for (int p = 0; p < 8; p++) {
            float zx = zbuf[p];
            int tn = t0 + 8 + p;
            if (tn < T_STEPS) zbuf[p] = zp[(size_t)tn * ZS];   // prefetch ~8 steps ahead

            float z  = fmaf(s, whs, zx);
            float cz = __cosf(z);
            cz += __shfl_xor_sync(0xffffffffu, cz, 1);
            cz += __shfl_xor_sync(0xffffffffu, cz, 2);
            cz += __shfl_xor_sync(0xffffffffu, cz, 4);
            float tg  = tanh_fast(fmaf(cz, scale, off));
            float val = isU ? tg : fmaf(0.5f, tg, 0.5f);
            // one-level allgather of the 4 gate scalars (wire index w of each group)
            float f = __shfl_sync(0xffffffffu, val, w);
            float i = __shfl_sync(0xffffffffu, val, 8 + w);
            float u = __shfl_sync(0xffffffffu, val, 16 + w);
            float o = __shfl_sync(0xffffffffu, val, 24 + w);
            c = fmaf(f, c, i * u);
            s = o * tanh_fast(c);
            float4 v = make_float4(s, s, s, s);
            *(float4*)(op + (size_t)(t0 + p) * OS) = v;        // stacked[t][b][:]
        }
    }
    // hx = final h (== stacked[T-1]); cx = final c, both broadcast over H
    float4 vs = make_float4(s, s, s, s);
    *(float4*)(out + (size_t)T_STEPS * OS + (size_t)b * HID + l * 4) = vs;
    float4 vc = make_float4(c, c, c, c);
    *(float4*)(out + (size_t)T_STEPS * OS + OS + (size_t)b * HID + l * 4) = vc;
}

extern "C" void kernel_launch(void* const* d_in, const int* in_sizes, int n_in,
                              void* d_out, int out_size) {
    const float* X  = (const float*)d_in[0];
    const float* Wf = (const float*)d_in[1];
    const float* bf = (const float*)d_in[2];
    const float* Wi = (const float*)d_in[3];
    const float* bi = (const float*)d_in[4];
    const float* Wu = (const float*)d_in[5];
    const float* bu = (const float*)d_in[6];
    const float* Wo = (const float*)d_in[7];
    const float* bo = (const float*)d_in[8];
    float* out = (float*)d_out;

    cudaFuncSetAttribute(gemm_kernel, cudaFuncAttributeMaxDynamicSharedMemorySize,
                         GEMM_SMEM_BYTES);

    whsum_kernel<<<1, 32>>>(Wf, Wi, Wu, Wo);
    gemm_kernel<<<(T_STEPS * BATCH) / 128, 256, GEMM_SMEM_BYTES>>>(
        X, Wf, bf, Wi, bi, Wu, bu, Wo, bo);
    rnn_kernel<<<BATCH, 32>>>(out);
}

// round 2
// speedup vs baseline: 1.0729x; 1.0729x over previous
#include <cuda_runtime.h>
#include <cstdint>

#define T_STEPS 2048
#define BATCH   512
#define DIM     128
#define HID     128
#define NG      32          // 4 gates * 8 wires
#define GEMM_SMEM_BYTES ((128*132 + 32*128 + 32) * 4)

// 134 MB scratch for Zx = X @ Wx^T + b  (layout: [t*B+b][32])
__device__ float g_Z[(size_t)T_STEPS * BATCH * NG];
__device__ float g_whsum[NG];

typedef unsigned long long u64;

__device__ __forceinline__ float tanh_fast(float x) {
    float r; asm("tanh.approx.f32 %0, %1;" : "=f"(r) : "f"(x)); return r;
}
// packed fp32x2 FMA: d.lo = a.lo*b.lo + c.lo ; d.hi = a.hi*b.hi + c.hi
__device__ __forceinline__ u64 ffma2(u64 a, u64 b, u64 c) {
    u64 d; asm("fma.rn.f32x2 %0, %1, %2, %3;" : "=l"(d) : "l"(a), "l"(b), "l"(c));
    return d;
}

// ---------------- whsum: row sums of the H-part of each gate's W ----------------
// 32 warps, one per (gate,wire) row; lane sums 4 elems then butterfly-reduce.
__global__ void whsum_kernel(const float* __restrict__ Wf, const float* __restrict__ Wi,
                             const float* __restrict__ Wu, const float* __restrict__ Wo) {
    int n = threadIdx.x >> 5;          // 0..31
    int lane = threadIdx.x & 31;
    int g = n >> 3, w = n & 7;
    const float* W = (g == 0) ? Wf : (g == 1) ? Wi : (g == 2) ? Wu : Wo;
    const float4 v = *(const float4*)(W + w * (DIM + HID) + DIM + lane * 4);
    float s = v.x + v.y + v.z + v.w;
    s += __shfl_xor_sync(0xffffffffu, s, 1);
    s += __shfl_xor_sync(0xffffffffu, s, 2);
    s += __shfl_xor_sync(0xffffffffu, s, 4);
    s += __shfl_xor_sync(0xffffffffu, s, 8);
    s += __shfl_xor_sync(0xffffffffu, s, 16);
    if (lane == 0) g_whsum[n] = s;
}

// ---------------- GEMM: Z[m][n] = sum_k X[m][k] * W_n[k] + b_n ----------------
// M = T*B = 1,048,576 rows, N = 32, K = 128. 128-row tiles, 256 threads.
// fp32x2 packed FMAs: each u64 accumulator holds (even-k, odd-k) partial sums.
__global__ void __launch_bounds__(256, 2) gemm_kernel(
    const float* __restrict__ X,
    const float* __restrict__ Wf, const float* __restrict__ bf,
    const float* __restrict__ Wi, const float* __restrict__ bi,
    const float* __restrict__ Wu, const float* __restrict__ bu,
    const float* __restrict__ Wo, const float* __restrict__ bo) {
    extern __shared__ float sm[];
    float* Xs = sm;                    // [128][132]  (pitch 132 -> conflict-free f4)
    float* Ws = sm + 128 * 132;        // [32][128]
    float* bs = Ws + 32 * 128;         // [32]
    const int tid = threadIdx.x;
    const size_t m0 = (size_t)blockIdx.x * 128;

    // Stage W (gate-major columns: n = g*8+w), first 128 columns only (x-part)
#pragma unroll
    for (int i = 0; i < 16; i++) {
        int idx = tid + i * 256;       // 0..4095
        int n = idx >> 7, k = idx & 127;
        int g = n >> 3, w = n & 7;
        const float* W = (g == 0) ? Wf : (g == 1) ? Wi : (g == 2) ? Wu : Wo;
        Ws[n * 128 + k] = W[w * 256 + k];
    }
    if (tid < 32) {
        int g = tid >> 3, w = tid & 7;
        const float* bb = (g == 0) ? bf : (g == 1) ? bi : (g == 2) ? bu : bo;
        bs[tid] = bb[w];
    }
    // Stage X tile (128 rows x 128 floats) as float4
#pragma unroll
    for (int i = 0; i < 16; i++) {
        int idx = tid + i * 256;       // float4 index 0..4095
        int m = idx >> 5, j = idx & 31;
        float4 v = *(const float4*)(X + (m0 + m) * 128 + j * 4);
        *(float4*)(Xs + m * 132 + j * 4) = v;
    }
    __syncthreads();

    const int lane = tid & 31;
    const int n0 = (tid >> 5) * 4;     // warp-uniform n block -> broadcast LDS for B
    ulonglong2 acc[4][4];
#pragma unroll
    for (int j = 0; j < 4; j++)
#pragma unroll
        for (int i = 0; i < 4; i++) { acc[j][i].x = 0ull; acc[j][i].y = 0ull; }

#pragma unroll 4
    for (int k = 0; k < 128; k += 4) {
        ulonglong2 A[4], Bv[4];
#pragma unroll
        for (int j = 0; j < 4; j++)
            A[j] = *(const ulonglong2*)(Xs + (lane + 32 * j) * 132 + k);
#pragma unroll
        for (int i = 0; i < 4; i++)
            Bv[i] = *(const ulonglong2*)(Ws + (n0 + i) * 128 + k);
#pragma unroll
        for (int j = 0; j < 4; j++)
#pragma unroll
            for (int i = 0; i < 4; i++) {
                acc[j][i].x = ffma2(A[j].x, Bv[i].x, acc[j][i].x);
                acc[j][i].y = ffma2(A[j].y, Bv[i].y, acc[j][i].y);
            }
    }
    __syncthreads();
    // Stage Z tile in smem (pitch 36) so global stores are fully coalesced
    float* Zs = sm;                    // reuse Xs region (bs region is disjoint)
#pragma unroll
    for (int j = 0; j < 4; j++)
#pragma unroll
        for (int i = 0; i < 4; i++) {
            float2 lo = *(float2*)&acc[j][i].x;
            float2 hi = *(float2*)&acc[j][i].y;
            Zs[(lane + 32 * j) * 36 + n0 + i] = (lo.x + lo.y) + (hi.x + hi.y) + bs[n0 + i];
        }
    __syncthreads();
#pragma unroll
    for (int i = 0; i < 4; i++) {
        int idx = tid + i * 256;       // 0..1023 float4s
        int m = idx >> 3, q = idx & 7;
        float4 v = *(const float4*)(Zs + m * 36 + q * 4);
        *(float4*)(g_Z + (m0 + m) * 32 + q * 4) = v;
    }
}

// ---------------- Recurrence: one warp per batch sample ----------------
// lanes 0..15 do the math (lanes 16..31 mirror); lane l2 = l&15 handles gate
// g = l2>>2, wires 2p and 2p+1 (p = l2&3). Two parallel MUFU.COS per lane,
// then a 2-stage butterfly (xor1, xor2) gives the 8-wire cosine sum per gate.
// qgate = mean(sin^2(z/2)) = 0.5 - (sum_w cos z_w)/16
// sigmoid(q) = 0.5 + 0.5*tanh(q/2); tanh gate uses tanh(q) directly.
__global__ void __launch_bounds__(32) rnn_kernel(float* __restrict__ out) {
    const int b = blockIdx.x;          // 512 chains
    const int l = threadIdx.x;
    const int l2 = l & 15;
    const int g = l2 >> 2;
    const int p = l2 & 3;
    const float whs0 = g_whsum[g * 8 + 2 * p];
    const float whs1 = g_whsum[g * 8 + 2 * p + 1];
    // fold the /2 for sigmoid gates into the q affine: arg = off + scale*sumcos
    const float scale = (g == 2) ? -(1.f / 16.f) : -(1.f / 32.f);
    const float off   = (g == 2) ? 0.5f : 0.25f;
    const float vm    = (g == 2) ? 1.0f : 0.5f;   // val = vm*tg + va (folds sigmoid)
    const float va    = (g == 2) ? 0.0f : 0.5f;

    const float* zp = g_Z + (size_t)b * NG + g * 8 + 2 * p;
    const size_t ZS = (size_t)BATCH * NG;    // 16384 floats per t
    const size_t OS = (size_t)BATCH * HID;   // 65536 floats per t
    float* op = out + (size_t)b * HID + (size_t)l * 4;

    float s = 0.f, c = 0.f;
    float2 zbuf[8];
#pragma unroll
    for (int q = 0; q < 8; q++) zbuf[q] = *(const float2*)(zp + (size_t)q * ZS);

    for (int t0 = 0; t0 < T_STEPS; t0 += 8) {
#pragma unroll
        for (int q = 0; q < 8; q++) {
            float2 zb = zbuf[q];
            int tn = t0 + 8 + q;
            if (tn < T_STEPS) zbuf[q] = *(const float2*)(zp + (size_t)tn * ZS);

            float z0 = fmaf(s, whs0, zb.x);
            float z1 = fmaf(s, whs1, zb.y);
            float cz = __cosf(z0) + __cosf(z1);
            cz += __shfl_xor_sync(0xffffffffu, cz, 1);
            cz += __shfl_xor_sync(0xffffffffu, cz, 2);
            float tg  = tanh_fast(fmaf(cz, scale, off));
            float val = fmaf(vm, tg, va);
            // gather the 4 gate scalars (groups live at lanes g*4 + p)
            float f = __shfl_sync(0xffffffffu, val, (l & 3));
            float i = __shfl_sync(0xffffffffu, val, 4 + (l & 3));
            float u = __shfl_sync(0xffffffffu, val, 8 + (l & 3));
            float o = __shfl_sync(0xffffffffu, val, 12 + (l & 3));
            c = fmaf(f, c, i * u);
            s = o * tanh_fast(c);
            float4 v = make_float4(s, s, s, s);
            *(float4*)(op + (size_t)(t0 + q) * OS) = v;        // stacked[t][b][:]
        }
    }
    // hx = final h (== stacked[T-1]); cx = final c, both broadcast over H
    float4 vs = make_float4(s, s, s, s);
    *(float4*)(out + (size_t)T_STEPS * OS + (size_t)b * HID + l * 4) = vs;
    float4 vc = make_float4(c, c, c, c);
    *(float4*)(out + (size_t)T_STEPS * OS + OS + (size_t)b * HID + l * 4) = vc;
}

extern "C" void kernel_launch(void* const* d_in, const int* in_sizes, int n_in,
                              void* d_out, int out_size) {
    const float* X  = (const float*)d_in[0];
    const float* Wf = (const float*)d_in[1];
    const float* bf = (const float*)d_in[2];
    const float* Wi = (const float*)d_in[3];
    const float* bi = (const float*)d_in[4];
    const float* Wu = (const float*)d_in[5];
    const float* bu = (const float*)d_in[6];
    const float* Wo = (const float*)d_in[7];
    const float* bo = (const float*)d_in[8];
    float* out = (float*)d_out;

    cudaFuncSetAttribute(gemm_kernel, cudaFuncAttributeMaxDynamicSharedMemorySize,
                         GEMM_SMEM_BYTES);

    whsum_kernel<<<1, 1024>>>(Wf, Wi, Wu, Wo);
    gemm_kernel<<<(T_STEPS * BATCH) / 128, 256, GEMM_SMEM_BYTES>>>(
        X, Wf, bf, Wi, bi, Wu, bu, Wo, bo);
    rnn_kernel<<<BATCH, 32>>>(out);
}

// round 3
// speedup vs baseline: 1.1119x; 1.0364x over previous
#include <cuda_runtime.h>
#include <cstdint>
#include <math.h>

#define T_STEPS 2048
#define BATCH   512
#define DIM     128
#define HID     128
#define NG      32          // 4 gates * 8 wires
#define GEMM_SMEM_BYTES ((128*132 + 32*128 + 32) * 4)

// scratch: Zx = X @ Wx^T + b  (layout [t*B+b][32]) and poly coeffs A
__device__ float g_Z[(size_t)T_STEPS * BATCH * NG];
__device__ float g_A[(size_t)T_STEPS * BATCH * NG];   // [row][gate][8 coeffs]
__device__ float g_whsum[NG];
__device__ float g_PC[4][8][4];   // [jj][w][g]  coeff of ca_w in a_{2jj}
__device__ float g_PS[4][8][4];   // [jj][w][g]  coeff of sa_w in a_{2jj+1}

typedef unsigned long long u64;

__device__ __forceinline__ float tanh_fast(float x) {
    float r; asm("tanh.approx.f32 %0, %1;" : "=f"(r) : "f"(x)); return r;
}
__device__ __forceinline__ u64 ffma2(u64 a, u64 b, u64 c) {
    u64 d; asm("fma.rn.f32x2 %0, %1, %2, %3;" : "=l"(d) : "l"(a), "l"(b), "l"(c));
    return d;
}

// ---------------- GEMM: Z[m][n] = sum_k X[m][k] * W_n[k] + b_n ----------------
__global__ void __launch_bounds__(256, 2) gemm_kernel(
    const float* __restrict__ X,
    const float* __restrict__ Wf, const float* __restrict__ bf,
    const float* __restrict__ Wi, const float* __restrict__ bi,
    const float* __restrict__ Wu, const float* __restrict__ bu,
    const float* __restrict__ Wo, const float* __restrict__ bo) {
    extern __shared__ float sm[];
    float* Xs = sm;                    // [128][132]
    float* Ws = sm + 128 * 132;        // [32][128]
    float* bs = Ws + 32 * 128;         // [32]
    const int tid = threadIdx.x;
    const size_t m0 = (size_t)blockIdx.x * 128;

#pragma unroll
    for (int i = 0; i < 16; i++) {
        int idx = tid + i * 256;
        int n = idx >> 7, k = idx & 127;
        int g = n >> 3, w = n & 7;
        const float* W = (g == 0) ? Wf : (g == 1) ? Wi : (g == 2) ? Wu : Wo;
        Ws[n * 128 + k] = W[w * 256 + k];
    }
    if (tid < 32) {
        int g = tid >> 3, w = tid & 7;
        const float* bb = (g == 0) ? bf : (g == 1) ? bi : (g == 2) ? bu : bo;
        bs[tid] = bb[w];
    }
#pragma unroll
    for (int i = 0; i < 16; i++) {
        int idx = tid + i * 256;
        int m = idx >> 5, j = idx & 31;
        float4 v = *(const float4*)(X + (m0 + m) * 128 + j * 4);
        *(float4*)(Xs + m * 132 + j * 4) = v;
    }
    __syncthreads();

    const int lane = tid & 31;
    const int n0 = (tid >> 5) * 4;
    ulonglong2 acc[4][4];
#pragma unroll
    for (int j = 0; j < 4; j++)
#pragma unroll
        for (int i = 0; i < 4; i++) { acc[j][i].x = 0ull; acc[j][i].y = 0ull; }

#pragma unroll 4
    for (int k = 0; k < 128; k += 4) {
        ulonglong2 A[4], Bv[4];
#pragma unroll
        for (int j = 0; j < 4; j++)
            A[j] = *(const ulonglong2*)(Xs + (lane + 32 * j) * 132 + k);
#pragma unroll
        for (int i = 0; i < 4; i++)
            Bv[i] = *(const ulonglong2*)(Ws + (n0 + i) * 128 + k);
#pragma unroll
        for (int j = 0; j < 4; j++)
#pragma unroll
            for (int i = 0; i < 4; i++) {
                acc[j][i].x = ffma2(A[j].x, Bv[i].x, acc[j][i].x);
                acc[j][i].y = ffma2(A[j].y, Bv[i].y, acc[j][i].y);
            }
    }
    __syncthreads();
    float* Zs = sm;
#pragma unroll
    for (int j = 0; j < 4; j++)
#pragma unroll
        for (int i = 0; i < 4; i++) {
            float2 lo = *(float2*)&acc[j][i].x;
            float2 hi = *(float2*)&acc[j][i].y;
            Zs[(lane + 32 * j) * 36 + n0 + i] = (lo.x + lo.y) + (hi.x + hi.y) + bs[n0 + i];
        }
    __syncthreads();
#pragma unroll
    for (int i = 0; i < 4; i++) {
        int idx = tid + i * 256;
        int m = idx >> 3, q = idx & 7;
        float4 v = *(const float4*)(Zs + m * 36 + q * 4);
        *(float4*)(g_Z + (m0 + m) * 32 + q * 4) = v;
    }
}

// ---------------- init: whsum + Chebyshev/Lagrange coefficient tables ----------------
// Interpolate q*sc (sc=1/2 for sigmoid gates, 1 for tanh gate) as a degree-7
// polynomial in s on [-0.75, 0.75]. q*sc = off - m*sum_w [ca_w cos(whs_w s) - sa_w sin(whs_w s)].
// By node symmetry, cos-terms hit only even monomials, sin-terms only odd.
__global__ void init_kernel(const float* __restrict__ Wf, const float* __restrict__ Wi,
                            const float* __restrict__ Wu, const float* __restrict__ Wo) {
    __shared__ double sL[8][8];        // [node k][monomial j]
    const int n = threadIdx.x;         // 0..31
    const int g = n >> 3, w = n & 7;
    const float* W = (g == 0) ? Wf : (g == 1) ? Wi : (g == 2) ? Wu : Wo;
    float s = 0.f;
#pragma unroll
    for (int k = 0; k < 128; k++) s += W[w * 256 + 128 + k];
    g_whsum[n] = s;

    double xk[8];
#pragma unroll
    for (int k = 0; k < 8; k++) xk[k] = 0.75 * cos((2.0 * k + 1.0) * M_PI / 16.0);

    if (n < 8) {   // Lagrange basis L_n -> monomial coeffs (double)
        double cf[8];
        for (int i = 0; i < 8; i++) cf[i] = 0.0;
        cf[0] = 1.0;
        double den = 1.0;
        int deg = 0;
        for (int j = 0; j < 8; j++) {
            if (j == n) continue;
            for (int i = deg + 1; i >= 1; i--) cf[i] = cf[i - 1] - xk[j] * cf[i];
            cf[0] = -xk[j] * cf[0];
            deg++;
            den *= (xk[n] - xk[j]);
        }
        for (int j = 0; j < 8; j++) sL[n][j] = cf[j] / den;
    }
    __syncthreads();

    const double m = (g == 2) ? (1.0 / 16.0) : (1.0 / 32.0);
    for (int jj = 0; jj < 4; jj++) {
        double pc = 0.0, ps = 0.0;
        for (int k = 0; k < 8; k++) {
            double th = (double)s * xk[k];
            pc += sL[k][2 * jj]     * cos(th);
            ps += sL[k][2 * jj + 1] * sin(th);
        }
        g_PC[jj][w][g] = (float)(-m * pc);
        g_PS[jj][w][g] = (float)( m * ps);
    }
}

// ---------------- eval: Z -> per-(row,gate) degree-7 poly coefficients ----------------
// thread handles (2 rows, 1 gate). 256 threads/block -> 128 rows/block.
__global__ void __launch_bounds__(256) eval_kernel() {
    __shared__ float sPC[4][8][4], sPS[4][8][4];
    const int tid = threadIdx.x;
    if (tid < 128) ((float*)sPC)[tid] = ((const float*)g_PC)[tid];
    else if (tid < 256) ((float*)sPS)[tid - 128] = ((const float*)g_PS)[tid - 128];
    __syncthreads();

    const int g = tid & 3;
    const size_t row0 = (size_t)blockIdx.x * 128 + (size_t)(tid >> 2) * 2;
    const float off = (g == 2) ? 0.5f : 0.25f;

    float ca0[8], sa0[8], ca1[8], sa1[8];
    {
        const float4* zp0 = (const float4*)(g_Z + row0 * 32 + g * 8);
        const float4* zp1 = (const float4*)(g_Z + (row0 + 1) * 32 + g * 8);
        float4 a = zp0[0], bq = zp0[1], cq = zp1[0], d = zp1[1];
        float z0[8] = {a.x, a.y, a.z, a.w, bq.x, bq.y, bq.z, bq.w};
        float z1[8] = {cq.x, cq.y, cq.z, cq.w, d.x, d.y, d.z, d.w};
#pragma unroll
        for (int w = 0; w < 8; w++) {
            ca0[w] = __cosf(z0[w]); sa0[w] = __sinf(z0[w]);
            ca1[w] = __cosf(z1[w]); sa1[w] = __sinf(z1[w]);
        }
    }
    float ae0[4] = {off, 0.f, 0.f, 0.f}, ao0[4] = {0.f, 0.f, 0.f, 0.f};
    float ae1[4] = {off, 0.f, 0.f, 0.f}, ao1[4] = {0.f, 0.f, 0.f, 0.f};
#pragma unroll
    for (int w = 0; w < 8; w++)
#pragma unroll
        for (int jj = 0; jj < 4; jj++) {
            float pc = sPC[jj][w][g], ps = sPS[jj][w][g];
            ae0[jj] = fmaf(ca0[w], pc, ae0[jj]);
            ao0[jj] = fmaf(sa0[w], ps, ao0[jj]);
            ae1[jj] = fmaf(ca1[w], pc, ae1[jj]);
            ao1[jj] = fmaf(sa1[w], ps, ao1[jj]);
        }
    float4* op0 = (float4*)(g_A + row0 * 32 + g * 8);
    float4* op1 = (float4*)(g_A + (row0 + 1) * 32 + g * 8);
    op0[0] = make_float4(ae0[0], ao0[0], ae0[1], ao0[1]);
    op0[1] = make_float4(ae0[2], ao0[2], ae0[3], ao0[3]);
    op1[0] = make_float4(ae1[0], ao1[0], ae1[1], ao1[1]);
    op1[1] = make_float4(ae1[2], ao1[2], ae1[3], ao1[3]);
}

// ---------------- rnn: one warp per chain; lanes 0-3 evaluate gate polys ----------------
__global__ void __launch_bounds__(32) rnn_kernel(float* __restrict__ out) {
    const int b = blockIdx.x;
    const int l = threadIdx.x;
    const int g = l & 3;
    const bool ldr = (l < 4);
    const float vm = (g == 2) ? 1.0f : 0.5f;
    const float va = (g == 2) ? 0.0f : 0.5f;

    const float* ap = g_A + (size_t)b * NG + g * 8;
    const size_t ASTR = (size_t)BATCH * NG;   // floats per t-step
    const size_t OS   = (size_t)BATCH * HID;
    float* op = out + (size_t)b * HID + (size_t)l * 4;

    float4 p0[16], p1[16];
#pragma unroll
    for (int q = 0; q < 16; q++) {
        if (ldr) {
            p0[q] = *(const float4*)(ap + (size_t)q * ASTR);
            p1[q] = *(const float4*)(ap + (size_t)q * ASTR + 4);
        }
    }
    float s = 0.f, c = 0.f;
    for (int t0 = 0; t0 < T_STEPS; t0 += 16) {
#pragma unroll
        for (int q = 0; q < 16; q++) {
            float4 A0 = p0[q], A1 = p1[q];
            int tn = t0 + 16 + q;
            if (ldr && tn < T_STEPS) {
                p0[q] = *(const float4*)(ap + (size_t)tn * ASTR);
                p1[q] = *(const float4*)(ap + (size_t)tn * ASTR + 4);
            }
            // Estrin degree-7: coeffs (a0..a7) = (A0.x,A0.y,A0.z,A0.w,A1.x..)
            float s2 = s * s, s4 = s2 * s2;
            float b0 = fmaf(A0.y, s, A0.x);
            float b1 = fmaf(A0.w, s, A0.z);
            float b2 = fmaf(A1.y, s, A1.x);
            float b3 = fmaf(A1.w, s, A1.z);
            float c0 = fmaf(b1, s2, b0);
            float c1 = fmaf(b3, s2, b2);
            float qv = fmaf(c1, s4, c0);
            float val = fmaf(vm, tanh_fast(qv), va);
            float f = __shfl_sync(0xffffffffu, val, 0);
            float i = __shfl_sync(0xffffffffu, val, 1);
            float u = __shfl_sync(0xffffffffu, val, 2);
            float o = __shfl_sync(0xffffffffu, val, 3);
            c = fmaf(f, c, i * u);
            s = o * tanh_fast(c);
            float4 v = make_float4(s, s, s, s);
            *(float4*)(op + (size_t)(t0 + q) * OS) = v;
        }
    }
    float4 vs = make_float4(s, s, s, s);
    *(float4*)(out + (size_t)T_STEPS * OS + (size_t)b * HID + l * 4) = vs;
    float4 vc = make_float4(c, c, c, c);
    *(float4*)(out + (size_t)T_STEPS * OS + OS + (size_t)b * HID + l * 4) = vc;
}

extern "C" void kernel_launch(void* const* d_in, const int* in_sizes, int n_in,
                              void* d_out, int out_size) {
    const float* X  = (const float*)d_in[0];
    const float* Wf = (const float*)d_in[1];
    const float* bf = (const float*)d_in[2];
    const float* Wi = (const float*)d_in[3];
    const float* bi = (const float*)d_in[4];
    const float* Wu = (const float*)d_in[5];
    const float* bu = (const float*)d_in[6];
    const float* Wo = (const float*)d_in[7];
    const float* bo = (const float*)d_in[8];
    float* out = (float*)d_out;

    cudaFuncSetAttribute(gemm_kernel, cudaFuncAttributeMaxDynamicSharedMemorySize,
                         GEMM_SMEM_BYTES);

    // gemm first so the ncu first-launch capture profiles it
    gemm_kernel<<<(T_STEPS * BATCH) / 128, 256, GEMM_SMEM_BYTES>>>(
        X, Wf, bf, Wi, bi, Wu, bu, Wo, bo);
    init_kernel<<<1, 32>>>(Wf, Wi, Wu, Wo);
    eval_kernel<<<(T_STEPS * BATCH) / 128, 256>>>();
    rnn_kernel<<<BATCH, 32>>>(out);
}